// round 4
// baseline (speedup 1.0000x reference)
#include <cuda_runtime.h>
#include <cuda_bf16.h>
#include <cstdint>

#define NNODES 50000
#define NEDGES 600000
#define NFEAT  128
#define F2     256
#define CF     384
#define HID    512
#define NOUT   128
#define NGR    128

// ---------------- scratch (static device globals; aligned; no runtime allocation) ----------------
__device__ __align__(256) int   g_scnt[NNODES];      // out-degree (src counts)
__device__ __align__(256) float g_dinv[NNODES];
__device__ __align__(256) int   g_cnt[NNODES];       // in-degree (dst counts) for CSR
__device__ __align__(256) int   g_rowptr[NNODES + 1];
__device__ __align__(256) int   g_cursor[NNODES];
__device__ __align__(256) int   g_csr_src[NEDGES];
__device__ __align__(256) float g_csr_w[NEDGES];
__device__ __align__(256) float g_Tx1[(size_t)NNODES * NFEAT];
__device__ __align__(256) float g_Tx2[(size_t)NNODES * NFEAT];
__device__ __align__(256) float g_gx1[(size_t)NNODES * NFEAT];
__device__ __align__(256) float g_gx2[(size_t)NNODES * F2];
__device__ __align__(256) int   g_goff[NGR + 1];
__device__ __align__(256) float g_pool[NGR * CF];
__device__ __align__(256) float g_h[NGR * HID];
__device__ int g_is64;   // 1 if integer inputs are int64, 0 if int32

// Buffer selector: 1=g_Tx1, 2=g_Tx2, 3=g_gx1, 4=g_gx2, 0=external (feature param)
template <int ID>
__device__ __forceinline__ float* bufptr(const float* ext) {
    if (ID == 1) return g_Tx1;
    if (ID == 2) return g_Tx2;
    if (ID == 3) return g_gx1;
    if (ID == 4) return g_gx2;
    return (float*)ext;
}

// Load integer index i from a buffer whose dtype (int32/int64) is given by g_is64.
__device__ __forceinline__ int load_idx(const void* p, long long i, int is64) {
    if (is64) return (int)((const long long*)p)[i];
    return ((const int*)p)[i];
}

// ---------------- dtype detection ----------------
// int64 node ids < 2^31 have all-zero odd 32-bit words; int32 random ids do not.
__global__ void detect_kernel(const void* ei) {
    const int* p = (const int*)ei;
    int orv = 0;
    for (int i = 0; i < 64; i++) orv |= p[2 * i + 1];
    g_is64 = (orv == 0) ? 1 : 0;
}

// ---------------- setup kernels ----------------
__global__ void zero_kernel() {
    int i = blockIdx.x * blockDim.x + threadIdx.x;
    if (i < NNODES) { g_scnt[i] = 0; g_cnt[i] = 0; }
}

__global__ void deg_kernel(const void* __restrict__ ei) {
    int e = blockIdx.x * blockDim.x + threadIdx.x;
    if (e >= NEDGES) return;
    int is64 = g_is64;
    int s = load_idx(ei, e, is64);
    int d = load_idx(ei, (long long)NEDGES + e, is64);
    if (s < 0 || s >= NNODES || d < 0 || d >= NNODES) return;  // defensive
    atomicAdd(&g_scnt[s], 1);
    atomicAdd(&g_cnt[d], 1);
}

__global__ void dinv_kernel() {
    int i = blockIdx.x * blockDim.x + threadIdx.x;
    if (i >= NNODES) return;
    float d = (float)g_scnt[i];
    g_dinv[i] = (d > 0.f) ? rsqrtf(d) : 0.f;
}

// single-block exclusive scan of g_cnt -> g_rowptr (and g_cursor copy)
__global__ void __launch_bounds__(1024) scan_kernel() {
    __shared__ __align__(16) int sh[1024];
    __shared__ int sbase;
    int tid = threadIdx.x;
    if (tid == 0) sbase = 0;
    __syncthreads();
    for (int start = 0; start < NNODES; start += 1024) {
        int i = start + tid;
        int v = (i < NNODES) ? g_cnt[i] : 0;
        sh[tid] = v;
        __syncthreads();
        for (int off = 1; off < 1024; off <<= 1) {
            int t = (tid >= off) ? sh[tid - off] : 0;
            __syncthreads();
            sh[tid] += t;
            __syncthreads();
        }
        int incl = sh[tid];
        int base = sbase;
        if (i < NNODES) {
            int ex = base + incl - v;
            g_rowptr[i] = ex;
            g_cursor[i] = ex;
        }
        __syncthreads();
        if (tid == 1023) sbase = base + incl;
        __syncthreads();
    }
    if (tid == 0) g_rowptr[NNODES] = sbase;
}

__global__ void scatter_kernel(const void* __restrict__ ei) {
    int e = blockIdx.x * blockDim.x + threadIdx.x;
    if (e >= NEDGES) return;
    int is64 = g_is64;
    int s = load_idx(ei, e, is64);
    int d = load_idx(ei, (long long)NEDGES + e, is64);
    if (s < 0 || s >= NNODES || d < 0 || d >= NNODES) return;  // defensive
    float w = -g_dinv[s] * g_dinv[d];
    int pos = atomicAdd(&g_cursor[d], 1);
    g_csr_src[pos] = s;
    g_csr_w[pos]   = w;
}

// ---------------- sparse propagation: out[dst] = alpha * sum_e w*x[src] (- xprev[dst]) ----------------
template <int XID, int PID, int OID>
__global__ void prop_kernel(const float* __restrict__ ext, float alpha) {
    const float* x = bufptr<XID>(ext);
    float* out = bufptr<OID>(ext);
    int warp = (blockIdx.x * blockDim.x + threadIdx.x) >> 5;
    if (warp >= NNODES) return;
    int lane = threadIdx.x & 31;
    int beg = g_rowptr[warp];
    int end = g_rowptr[warp + 1];
    float4 acc = make_float4(0.f, 0.f, 0.f, 0.f);
    for (int j = beg; j < end; j++) {
        int s   = g_csr_src[j];
        float w = g_csr_w[j];
        const float4 v = *(const float4*)(x + (size_t)s * NFEAT + lane * 4);
        acc.x += w * v.x; acc.y += w * v.y; acc.z += w * v.z; acc.w += w * v.w;
    }
    size_t o = (size_t)warp * NFEAT + lane * 4;
    if (PID >= 0) {
        const float* xprev = bufptr<(PID >= 0 ? PID : 0)>(ext);
        const float4 p = *(const float4*)(xprev + o);
        acc.x = alpha * acc.x - p.x;
        acc.y = alpha * acc.y - p.y;
        acc.z = alpha * acc.z - p.z;
        acc.w = alpha * acc.w - p.w;
    }
    *(float4*)(out + o) = acc;
}

// ---------------- fused 3-term GEMM: out = relu(X0@W[0] + X1@W[1] + X2@W[2] + b) ----------------
// BM=128, BN=64, BK=16, 256 threads, 8x4 per thread
template <int FOUT, int X0ID, int X1ID, int X2ID, int OID>
__global__ void __launch_bounds__(256) gemm3_kernel(
    const float* __restrict__ ext,
    const float* __restrict__ W, const float* __restrict__ bias) {
    const float* X0 = bufptr<X0ID>(ext);
    const float* X1 = bufptr<X1ID>(ext);
    const float* X2 = bufptr<X2ID>(ext);
    float* out = bufptr<OID>(ext);

    __shared__ __align__(16) float Xs[16][132];  // [k][row], padded
    __shared__ __align__(16) float Ws[16][64];

    int tid  = threadIdx.x;
    int row0 = blockIdx.x * 128;
    int col0 = blockIdx.y * 64;
    int tx = tid & 15;   // 0..15 -> cols tx*4..tx*4+3
    int ty = tid >> 4;   // 0..15 -> rows ty*8..ty*8+7

    int lrow = tid >> 2;          // 0..63 (two passes)
    int lk4  = (tid & 3) * 4;     // 0,4,8,12
    int wrow = tid >> 4;          // 0..15 (k)
    int wcol4 = (tid & 15) * 4;

    float acc[8][4];
#pragma unroll
    for (int i = 0; i < 8; i++)
#pragma unroll
        for (int j = 0; j < 4; j++) acc[i][j] = 0.f;

    for (int kt = 0; kt < 24; kt++) {
        int t  = kt >> 3;
        int k0 = (kt & 7) * 16;
        const float* X = (t == 0) ? X0 : ((t == 1) ? X1 : X2);

#pragma unroll
        for (int p = 0; p < 2; p++) {
            int r = lrow + p * 64;
            int grow = row0 + r;
            float4 v = make_float4(0.f, 0.f, 0.f, 0.f);
            if (grow < NNODES)
                v = *(const float4*)(X + (size_t)grow * NFEAT + k0 + lk4);
            Xs[lk4 + 0][r] = v.x;
            Xs[lk4 + 1][r] = v.y;
            Xs[lk4 + 2][r] = v.z;
            Xs[lk4 + 3][r] = v.w;
        }
        *(float4*)&Ws[wrow][wcol4] =
            *(const float4*)(W + ((size_t)t * NFEAT + k0 + wrow) * FOUT + col0 + wcol4);
        __syncthreads();

#pragma unroll
        for (int k = 0; k < 16; k++) {
            float4 a0 = *(const float4*)&Xs[k][ty * 8];
            float4 a1 = *(const float4*)&Xs[k][ty * 8 + 4];
            float4 b4 = *(const float4*)&Ws[k][tx * 4];
            float a[8] = {a0.x, a0.y, a0.z, a0.w, a1.x, a1.y, a1.z, a1.w};
            float b[4] = {b4.x, b4.y, b4.z, b4.w};
#pragma unroll
            for (int i = 0; i < 8; i++)
#pragma unroll
                for (int j = 0; j < 4; j++) acc[i][j] += a[i] * b[j];
        }
        __syncthreads();
    }

#pragma unroll
    for (int i = 0; i < 8; i++) {
        int grow = row0 + ty * 8 + i;
        if (grow >= NNODES) continue;
#pragma unroll
        for (int j = 0; j < 4; j++) {
            int c = col0 + tx * 4 + j;
            float v = acc[i][j] + bias[c];
            v = fmaxf(v, 0.f);
            out[(size_t)grow * FOUT + c] = v;
        }
    }
}

// ---------------- pooling ----------------
__global__ void goff_kernel(const void* __restrict__ batch) {
    int g = blockIdx.x * blockDim.x + threadIdx.x;
    if (g > NGR) return;
    int is64 = g_is64;
    int lo = 0, hi = NNODES;
    while (lo < hi) {
        int mid = (lo + hi) >> 1;
        int v = load_idx(batch, mid, is64);
        if (v < g) lo = mid + 1;
        else hi = mid;
    }
    g_goff[g] = lo;
}

__global__ void pool_kernel(const float* __restrict__ feat) {
    int g = blockIdx.x;
    int c = threadIdx.x;  // 0..383
    int lo = g_goff[g], hi = g_goff[g + 1];
    float s = 0.f;
    if (c < F2) {
        for (int r = lo; r < hi; r++) s += g_gx2[(size_t)r * F2 + c];
    } else {
        int cc = c - F2;
        for (int r = lo; r < hi; r++) s += feat[(size_t)r * NFEAT + cc];
    }
    float cnt = (float)(hi - lo);
    g_pool[g * CF + c] = s / fmaxf(cnt, 1.f);
}

// ---------------- FC layers ----------------
__global__ void fc1_kernel(const float* __restrict__ Wm, const float* __restrict__ b) {
    int idx = blockIdx.x * blockDim.x + threadIdx.x;
    if (idx >= NGR * HID) return;
    int m = idx / HID, n = idx % HID;
    float s = b[n];
    const float* a = &g_pool[m * CF];
    for (int k = 0; k < CF; k++) s += a[k] * Wm[(size_t)k * HID + n];
    g_h[idx] = fmaxf(s, 0.f);
}

__global__ void fc2_kernel(const float* __restrict__ Wm, const float* __restrict__ b,
                           float* __restrict__ out) {
    int idx = blockIdx.x * blockDim.x + threadIdx.x;
    if (idx >= NGR * NOUT) return;
    int m = idx / NOUT, n = idx % NOUT;
    float s = b[n];
    const float* a = &g_h[m * HID];
    for (int k = 0; k < HID; k++) s += a[k] * Wm[(size_t)k * NOUT + n];
    out[idx] = s;
}

// ---------------- launch ----------------
extern "C" void kernel_launch(void* const* d_in, const int* in_sizes, int n_in,
                              void* d_out, int out_size) {
    // Size-based input identification (robust to metadata ordering).
    const float* feature = nullptr;
    const void* ei = nullptr;
    const void* pbatch = nullptr;
    const float *W1 = nullptr, *b1 = nullptr, *W2 = nullptr, *b2 = nullptr;
    const float *fc1_w = nullptr, *fc1_b = nullptr, *fc2_w = nullptr, *fc2_b = nullptr;
    int seen128 = 0;
    for (int i = 0; i < n_in; i++) {
        switch (in_sizes[i]) {
            case 6400000: feature = (const float*)d_in[i]; break;
            case 1200000: ei      = d_in[i]; break;
            case 50000:   pbatch  = d_in[i]; break;
            case 49152:   W1      = (const float*)d_in[i]; break;
            case 98304:   W2      = (const float*)d_in[i]; break;
            case 196608:  fc1_w   = (const float*)d_in[i]; break;
            case 512:     fc1_b   = (const float*)d_in[i]; break;
            case 65536:   fc2_w   = (const float*)d_in[i]; break;
            case 256:     b2      = (const float*)d_in[i]; break;
            case 128:
                if (seen128++ == 0) b1 = (const float*)d_in[i];
                else                fc2_b = (const float*)d_in[i];
                break;
            default: break;
        }
    }
    float* out = (float*)d_out;

    // ---- dtype detection + graph normalization + CSR build ----
    detect_kernel<<<1, 1>>>(ei);
    zero_kernel<<<(NNODES + 255) / 256, 256>>>();
    deg_kernel<<<(NEDGES + 255) / 256, 256>>>(ei);
    dinv_kernel<<<(NNODES + 255) / 256, 256>>>();
    scan_kernel<<<1, 1024>>>();
    scatter_kernel<<<(NEDGES + 255) / 256, 256>>>(ei);

    const int PROP_BLOCKS = (NNODES * 32 + 255) / 256;

    // ---- conv1 ----
    prop_kernel<0, -1, 1><<<PROP_BLOCKS, 256>>>(feature, 1.f);   // Tx1 = P @ x
    prop_kernel<1, 0, 2><<<PROP_BLOCKS, 256>>>(feature, 2.f);    // Tx2 = 2P@Tx1 - x
    {
        dim3 grid((NNODES + 127) / 128, NFEAT / 64);
        gemm3_kernel<NFEAT, 0, 1, 2, 3><<<grid, 256>>>(feature, W1, b1);
    }

    // ---- conv2 ----
    prop_kernel<3, -1, 1><<<PROP_BLOCKS, 256>>>(feature, 1.f);   // Tx1 = P @ gx1
    prop_kernel<1, 3, 2><<<PROP_BLOCKS, 256>>>(feature, 2.f);    // Tx2 = 2P@Tx1 - gx1
    {
        dim3 grid((NNODES + 127) / 128, F2 / 64);
        gemm3_kernel<F2, 3, 1, 2, 4><<<grid, 256>>>(feature, W2, b2);
    }

    // ---- pooling ----
    goff_kernel<<<1, 256>>>(pbatch);
    pool_kernel<<<NGR, CF>>>(feature);

    // ---- FC head ----
    fc1_kernel<<<(NGR * HID + 255) / 256, 256>>>(fc1_w, fc1_b);
    fc2_kernel<<<(NGR * NOUT + 255) / 256, 256>>>(fc2_w, fc2_b, out);
}

// round 6
// speedup vs baseline: 1.6081x; 1.6081x over previous
#include <cuda_runtime.h>
#include <cuda_bf16.h>
#include <cstdint>

#define NNODES 50000
#define NEDGES 600000
#define NFEAT  128
#define F2     256
#define CF     384
#define HID    512
#define NOUT   128
#define NGR    128

__device__ __forceinline__ float f2tf32(float x) {
    float y;
    asm("cvt.rna.tf32.f32 %0, %1;" : "=f"(y) : "f"(x));
    return y;
}

__device__ __forceinline__ void mma_tf32(float c[4], const uint32_t a[4], const uint32_t b[2]) {
    asm volatile(
        "mma.sync.aligned.m16n8k8.row.col.f32.tf32.tf32.f32 "
        "{%0,%1,%2,%3}, {%4,%5,%6,%7}, {%8,%9}, {%0,%1,%2,%3};"
        : "+f"(c[0]), "+f"(c[1]), "+f"(c[2]), "+f"(c[3])
        : "r"(a[0]), "r"(a[1]), "r"(a[2]), "r"(a[3]), "r"(b[0]), "r"(b[1]));
}

// ---------------- scratch (static device globals; aligned; no runtime allocation) ----------------
__device__ __align__(256) int   g_scnt[NNODES];
__device__ __align__(256) float g_dinv[NNODES];
__device__ __align__(256) int   g_cnt[NNODES];
__device__ __align__(256) int   g_rowptr[NNODES + 1];
__device__ __align__(256) int   g_cursor[NNODES];
__device__ __align__(256) int   g_csr_src[NEDGES];
__device__ __align__(256) float g_csr_w[NEDGES];
__device__ __align__(256) float g_Tx1[(size_t)NNODES * NFEAT];
__device__ __align__(256) float g_Tx2[(size_t)NNODES * NFEAT];
__device__ __align__(256) float g_gx1[(size_t)NNODES * NFEAT];
__device__ __align__(256) float g_gx2[(size_t)NNODES * F2];
__device__ __align__(256) float g_Wt1[NFEAT * CF];   // [128][384] tf32-rounded, transposed W1
__device__ __align__(256) float g_Wt2[F2 * CF];      // [256][384] tf32-rounded, transposed W2
__device__ __align__(256) int   g_goff[NGR + 1];
__device__ __align__(256) float g_pool[NGR * CF];
__device__ __align__(256) float g_h[NGR * HID];
__device__ int g_is64;

template <int ID>
__device__ __forceinline__ float* bufptr(const float* ext) {
    if (ID == 1) return g_Tx1;
    if (ID == 2) return g_Tx2;
    if (ID == 3) return g_gx1;
    if (ID == 4) return g_gx2;
    return (float*)ext;
}

__device__ __forceinline__ int load_idx(const void* p, long long i, int is64) {
    if (is64) return (int)((const long long*)p)[i];
    return ((const int*)p)[i];
}

// ---------------- dtype detection ----------------
__global__ void detect_kernel(const void* ei) {
    const int* p = (const int*)ei;
    int orv = 0;
    for (int i = 0; i < 64; i++) orv |= p[2 * i + 1];
    g_is64 = (orv == 0) ? 1 : 0;
}

// ---------------- setup kernels ----------------
__global__ void zero_kernel() {
    int i = blockIdx.x * blockDim.x + threadIdx.x;
    if (i < NNODES) { g_scnt[i] = 0; g_cnt[i] = 0; }
}

__global__ void deg_kernel(const void* __restrict__ ei) {
    int e = blockIdx.x * blockDim.x + threadIdx.x;
    if (e >= NEDGES) return;
    int is64 = g_is64;
    int s = load_idx(ei, e, is64);
    int d = load_idx(ei, (long long)NEDGES + e, is64);
    if (s < 0 || s >= NNODES || d < 0 || d >= NNODES) return;
    atomicAdd(&g_scnt[s], 1);
    atomicAdd(&g_cnt[d], 1);
}

__global__ void dinv_kernel() {
    int i = blockIdx.x * blockDim.x + threadIdx.x;
    if (i >= NNODES) return;
    float d = (float)g_scnt[i];
    g_dinv[i] = (d > 0.f) ? rsqrtf(d) : 0.f;
}

// single-block exclusive scan (warp-shuffle based)
__global__ void __launch_bounds__(1024) scan_kernel() {
    __shared__ int warpsum[32];
    __shared__ int sbase;
    int tid = threadIdx.x;
    int wid = tid >> 5, lane = tid & 31;
    if (tid == 0) sbase = 0;
    __syncthreads();
    for (int start = 0; start < NNODES; start += 1024) {
        int i = start + tid;
        int v = (i < NNODES) ? g_cnt[i] : 0;
        int x = v;
#pragma unroll
        for (int off = 1; off < 32; off <<= 1) {
            int n = __shfl_up_sync(0xFFFFFFFFu, x, off);
            if (lane >= off) x += n;
        }
        if (lane == 31) warpsum[wid] = x;
        __syncthreads();
        if (wid == 0) {
            int y = warpsum[lane];
#pragma unroll
            for (int off = 1; off < 32; off <<= 1) {
                int n = __shfl_up_sync(0xFFFFFFFFu, y, off);
                if (lane >= off) y += n;
            }
            warpsum[lane] = y;
        }
        __syncthreads();
        int incl = x + (wid > 0 ? warpsum[wid - 1] : 0);
        int base = sbase;
        if (i < NNODES) {
            int ex = base + incl - v;
            g_rowptr[i] = ex;
            g_cursor[i] = ex;
        }
        __syncthreads();
        if (tid == 1023) sbase = base + incl;
        __syncthreads();
    }
    if (threadIdx.x == 0) g_rowptr[NNODES] = sbase;
}

__global__ void scatter_kernel(const void* __restrict__ ei) {
    int e = blockIdx.x * blockDim.x + threadIdx.x;
    if (e >= NEDGES) return;
    int is64 = g_is64;
    int s = load_idx(ei, e, is64);
    int d = load_idx(ei, (long long)NEDGES + e, is64);
    if (s < 0 || s >= NNODES || d < 0 || d >= NNODES) return;
    float w = -g_dinv[s] * g_dinv[d];
    int pos = atomicAdd(&g_cursor[d], 1);
    g_csr_src[pos] = s;
    g_csr_w[pos]   = w;
}

// ---------------- sparse propagation ----------------
template <int XID, int PID, int OID>
__global__ void prop_kernel(const float* __restrict__ ext, float alpha) {
    const float* x = bufptr<XID>(ext);
    float* out = bufptr<OID>(ext);
    int warp = (blockIdx.x * blockDim.x + threadIdx.x) >> 5;
    if (warp >= NNODES) return;
    int lane = threadIdx.x & 31;
    int beg = g_rowptr[warp];
    int end = g_rowptr[warp + 1];
    float4 acc = make_float4(0.f, 0.f, 0.f, 0.f);
    for (int j = beg; j < end; j++) {
        int s   = g_csr_src[j];
        float w = g_csr_w[j];
        const float4 v = *(const float4*)(x + (size_t)s * NFEAT + lane * 4);
        acc.x += w * v.x; acc.y += w * v.y; acc.z += w * v.z; acc.w += w * v.w;
    }
    size_t o = (size_t)warp * NFEAT + lane * 4;
    if (PID >= 0) {
        const float* xprev = bufptr<(PID >= 0 ? PID : 0)>(ext);
        const float4 p = *(const float4*)(xprev + o);
        acc.x = alpha * acc.x - p.x;
        acc.y = alpha * acc.y - p.y;
        acc.z = alpha * acc.z - p.z;
        acc.w = alpha * acc.w - p.w;
    }
    *(float4*)(out + o) = acc;
}

// ---------------- weight transpose: W[3][128][FOUT] -> Wt[FOUT][384] (tf32-rounded) ----------------
template <int FOUT>
__global__ void wtrans_kernel(const float* __restrict__ W) {
    float* Wt = (FOUT == NFEAT) ? g_Wt1 : g_Wt2;
    int idx = blockIdx.x * blockDim.x + threadIdx.x;
    if (idx >= CF * FOUT) return;
    int kk = idx / FOUT;   // 0..383 (t*128 + k)
    int n  = idx % FOUT;
    Wt[(size_t)n * CF + kk] = f2tf32(W[idx]);
}

// ---------------- tf32 warp-MMA fused 3-term GEMM ----------------
// BM=128, BN=128, BK=32; 8 warps (2 x 4), warp tile 64x32; m16n8k8 mma.
// out = relu(sum_t Xt @ W[t] + b)
#define APAD 36
template <int FOUT, int X0ID, int X1ID, int X2ID, int OID>
__global__ void __launch_bounds__(256) gemm3_mma_kernel(
    const float* __restrict__ ext, const float* __restrict__ bias) {
    const float* X0 = bufptr<X0ID>(ext);
    const float* X1 = bufptr<X1ID>(ext);
    const float* X2 = bufptr<X2ID>(ext);
    const float* Wt = (FOUT == NFEAT) ? g_Wt1 : g_Wt2;
    float* out = bufptr<OID>(ext);

    __shared__ __align__(16) float As[128][APAD];  // [m][k]
    __shared__ __align__(16) float Bs[128][APAD];  // [n][k]

    int tid  = threadIdx.x;
    int wid  = tid >> 5;
    int lane = tid & 31;
    int wm = (wid & 1) * 64;   // warp m offset in tile
    int wn = (wid >> 1) * 32;  // warp n offset in tile
    int row0 = blockIdx.x * 128;
    int col0 = blockIdx.y * 128;

    int gp = lane >> 2;   // 0..7
    int tg = lane & 3;    // 0..3

    float acc[4][4][4];   // [mt][nt][reg]
#pragma unroll
    for (int i = 0; i < 4; i++)
#pragma unroll
        for (int j = 0; j < 4; j++)
#pragma unroll
            for (int r = 0; r < 4; r++) acc[i][j][r] = 0.f;

    for (int ch = 0; ch < 12; ch++) {
        int t  = ch >> 2;
        int k0 = (ch & 3) * 32;
        const float* X = (t == 0) ? X0 : ((t == 1) ? X1 : X2);

        // load A tile (rounded to tf32) and B tile (pre-rounded)
#pragma unroll
        for (int i = 0; i < 4; i++) {
            int idx = tid + i * 256;     // 0..1023
            int r   = idx >> 3;          // 0..127
            int c4  = (idx & 7) * 4;     // 0..28
            int grow = row0 + r;
            float4 va = make_float4(0.f, 0.f, 0.f, 0.f);
            if (grow < NNODES)
                va = *(const float4*)(X + (size_t)grow * NFEAT + k0 + c4);
            va.x = f2tf32(va.x); va.y = f2tf32(va.y);
            va.z = f2tf32(va.z); va.w = f2tf32(va.w);
            *(float4*)&As[r][c4] = va;
            float4 vb = *(const float4*)(Wt + (size_t)(col0 + r) * CF + t * NFEAT + k0 + c4);
            *(float4*)&Bs[r][c4] = vb;
        }
        __syncthreads();

#pragma unroll
        for (int ks = 0; ks < 4; ks++) {
            int kc = ks * 8 + tg;
            uint32_t afr[4][4];
#pragma unroll
            for (int mt = 0; mt < 4; mt++) {
                int m = wm + mt * 16 + gp;
                afr[mt][0] = __float_as_uint(As[m][kc]);
                afr[mt][1] = __float_as_uint(As[m + 8][kc]);
                afr[mt][2] = __float_as_uint(As[m][kc + 4]);
                afr[mt][3] = __float_as_uint(As[m + 8][kc + 4]);
            }
            uint32_t bfr[4][2];
#pragma unroll
            for (int nt = 0; nt < 4; nt++) {
                int n = wn + nt * 8 + gp;
                bfr[nt][0] = __float_as_uint(Bs[n][kc]);
                bfr[nt][1] = __float_as_uint(Bs[n][kc + 4]);
            }
#pragma unroll
            for (int mt = 0; mt < 4; mt++)
#pragma unroll
                for (int nt = 0; nt < 4; nt++)
                    mma_tf32(acc[mt][nt], afr[mt], bfr[nt]);
        }
        __syncthreads();
    }

    // epilogue: bias + relu, float2 stores
#pragma unroll
    for (int mt = 0; mt < 4; mt++) {
#pragma unroll
        for (int nt = 0; nt < 4; nt++) {
            int gcol = col0 + wn + nt * 8 + 2 * tg;
            float2 bv = *(const float2*)(bias + gcol);
            int r0 = row0 + wm + mt * 16 + gp;
            if (r0 < NNODES) {
                float2 o0;
                o0.x = fmaxf(acc[mt][nt][0] + bv.x, 0.f);
                o0.y = fmaxf(acc[mt][nt][1] + bv.y, 0.f);
                *(float2*)(out + (size_t)r0 * FOUT + gcol) = o0;
            }
            int r1 = r0 + 8;
            if (r1 < NNODES) {
                float2 o1;
                o1.x = fmaxf(acc[mt][nt][2] + bv.x, 0.f);
                o1.y = fmaxf(acc[mt][nt][3] + bv.y, 0.f);
                *(float2*)(out + (size_t)r1 * FOUT + gcol) = o1;
            }
        }
    }
}

// ---------------- pooling ----------------
__global__ void goff_kernel(const void* __restrict__ batch) {
    int g = blockIdx.x * blockDim.x + threadIdx.x;
    if (g > NGR) return;
    int is64 = g_is64;
    int lo = 0, hi = NNODES;
    while (lo < hi) {
        int mid = (lo + hi) >> 1;
        int v = load_idx(batch, mid, is64);
        if (v < g) lo = mid + 1;
        else hi = mid;
    }
    g_goff[g] = lo;
}

__global__ void pool_kernel(const float* __restrict__ feat) {
    int g = blockIdx.x;
    int c = threadIdx.x;  // 0..383
    int lo = g_goff[g], hi = g_goff[g + 1];
    float s = 0.f;
    if (c < F2) {
        for (int r = lo; r < hi; r++) s += g_gx2[(size_t)r * F2 + c];
    } else {
        int cc = c - F2;
        for (int r = lo; r < hi; r++) s += feat[(size_t)r * NFEAT + cc];
    }
    float cnt = (float)(hi - lo);
    g_pool[g * CF + c] = s / fmaxf(cnt, 1.f);
}

// ---------------- FC layers ----------------
__global__ void fc1_kernel(const float* __restrict__ Wm, const float* __restrict__ b) {
    int idx = blockIdx.x * blockDim.x + threadIdx.x;
    if (idx >= NGR * HID) return;
    int m = idx / HID, n = idx % HID;
    float s = b[n];
    const float* a = &g_pool[m * CF];
    for (int k = 0; k < CF; k++) s += a[k] * Wm[(size_t)k * HID + n];
    g_h[idx] = fmaxf(s, 0.f);
}

__global__ void fc2_kernel(const float* __restrict__ Wm, const float* __restrict__ b,
                           float* __restrict__ out) {
    int idx = blockIdx.x * blockDim.x + threadIdx.x;
    if (idx >= NGR * NOUT) return;
    int m = idx / NOUT, n = idx % NOUT;
    float s = b[n];
    const float* a = &g_h[m * HID];
    for (int k = 0; k < HID; k++) s += a[k] * Wm[(size_t)k * NOUT + n];
    out[idx] = s;
}

// ---------------- launch ----------------
extern "C" void kernel_launch(void* const* d_in, const int* in_sizes, int n_in,
                              void* d_out, int out_size) {
    const float* feature = nullptr;
    const void* ei = nullptr;
    const void* pbatch = nullptr;
    const float *W1 = nullptr, *b1 = nullptr, *W2 = nullptr, *b2 = nullptr;
    const float *fc1_w = nullptr, *fc1_b = nullptr, *fc2_w = nullptr, *fc2_b = nullptr;
    int seen128 = 0;
    for (int i = 0; i < n_in; i++) {
        switch (in_sizes[i]) {
            case 6400000: feature = (const float*)d_in[i]; break;
            case 1200000: ei      = d_in[i]; break;
            case 50000:   pbatch  = d_in[i]; break;
            case 49152:   W1      = (const float*)d_in[i]; break;
            case 98304:   W2      = (const float*)d_in[i]; break;
            case 196608:  fc1_w   = (const float*)d_in[i]; break;
            case 512:     fc1_b   = (const float*)d_in[i]; break;
            case 65536:   fc2_w   = (const float*)d_in[i]; break;
            case 256:     b2      = (const float*)d_in[i]; break;
            case 128:
                if (seen128++ == 0) b1 = (const float*)d_in[i];
                else                fc2_b = (const float*)d_in[i];
                break;
            default: break;
        }
    }
    float* out = (float*)d_out;

    // ---- dtype detection + graph normalization + CSR build + weight prep ----
    detect_kernel<<<1, 1>>>(ei);
    zero_kernel<<<(NNODES + 255) / 256, 256>>>();
    deg_kernel<<<(NEDGES + 255) / 256, 256>>>(ei);
    wtrans_kernel<NFEAT><<<(CF * NFEAT + 255) / 256, 256>>>(W1);
    wtrans_kernel<F2><<<(CF * F2 + 255) / 256, 256>>>(W2);
    dinv_kernel<<<(NNODES + 255) / 256, 256>>>();
    scan_kernel<<<1, 1024>>>();
    scatter_kernel<<<(NEDGES + 255) / 256, 256>>>(ei);

    const int PROP_BLOCKS = (NNODES * 32 + 255) / 256;

    // ---- conv1 ----
    prop_kernel<0, -1, 1><<<PROP_BLOCKS, 256>>>(feature, 1.f);   // Tx1 = P @ x
    prop_kernel<1, 0, 2><<<PROP_BLOCKS, 256>>>(feature, 2.f);    // Tx2 = 2P@Tx1 - x
    {
        dim3 grid((NNODES + 127) / 128, NFEAT / 128);
        gemm3_mma_kernel<NFEAT, 0, 1, 2, 3><<<grid, 256>>>(feature, b1);
    }

    // ---- conv2 ----
    prop_kernel<3, -1, 1><<<PROP_BLOCKS, 256>>>(feature, 1.f);   // Tx1 = P @ gx1
    prop_kernel<1, 3, 2><<<PROP_BLOCKS, 256>>>(feature, 2.f);    // Tx2 = 2P@Tx1 - gx1
    {
        dim3 grid((NNODES + 127) / 128, F2 / 128);
        gemm3_mma_kernel<F2, 3, 1, 2, 4><<<grid, 256>>>(feature, b2);
    }

    // ---- pooling ----
    goff_kernel<<<1, 256>>>(pbatch);
    pool_kernel<<<NGR, CF>>>(feature);

    // ---- FC head ----
    fc1_kernel<<<(NGR * HID + 255) / 256, 256>>>(fc1_w, fc1_b);
    fc2_kernel<<<(NGR * NOUT + 255) / 256, 256>>>(fc2_w, fc2_b, out);
}